// round 9
// baseline (speedup 1.0000x reference)
#include <cuda_runtime.h>
#include <cuda_fp16.h>
#include <math.h>

#define NN   50000
#define EE   800000
#define ETOT (EE + NN)
#define H1N  4
#define C1   256   // H1*64
#define C2   64
#define CAP  128   // per-destination adjacency capacity

#define BM 128
#define BN 64
#define BK 32
#define APAD 40    // As row stride in halves (80B; 16B-aligned, conflict-free frags)
#define BPAD 40    // Bs row stride in halves

// ---------------- scratch (device globals; no allocations allowed) ----------
__device__ __half g_h1[(size_t)NN * C1];
__device__ __half g_out1[(size_t)NN * C1];
__device__ __half g_h2[(size_t)NN * C2];
__device__ float  g_alsrc1[NN * H1N], g_aldst1[NN * H1N];
__device__ float  g_alsrc2[NN],       g_aldst2[NN];
__device__ int    g_cursor[NN];
__device__ int    g_csr[(size_t)NN * CAP];

// ---------------- helpers ----------------------------------------------------
__device__ __forceinline__ void mma_f16(float* c, const unsigned* a, const unsigned* b) {
    asm volatile("mma.sync.aligned.m16n8k16.row.col.f32.f16.f16.f32 "
        "{%0,%1,%2,%3}, {%4,%5,%6,%7}, {%8,%9}, {%0,%1,%2,%3};"
        : "+f"(c[0]), "+f"(c[1]), "+f"(c[2]), "+f"(c[3])
        : "r"(a[0]), "r"(a[1]), "r"(a[2]), "r"(a[3]), "r"(b[0]), "r"(b[1]));
}

// ---------------- adjacency build -------------------------------------------
__global__ void init_kernel() {
    int tid = blockIdx.x * blockDim.x + threadIdx.x;
    if (tid < NN) g_cursor[tid] = 0;
}
__global__ void fill_adj(const int* __restrict__ ei) {
    int e = blockIdx.x * blockDim.x + threadIdx.x;
    if (e >= ETOT) return;
    int s, d;
    if (e < EE) { s = ei[e]; d = ei[e + EE]; }
    else        { s = d = e - EE; }
    int pos = atomicAdd(&g_cursor[d], 1);
    if (pos < CAP) g_csr[(size_t)d * CAP + pos] = s;
}

// ---------------- fp16 HMMA GEMM + fused attention-coefficient epilogue ------
// A fp32 or fp16 (templated; fp16 staging is precision-neutral vs tf32);
// B fp32 -> fp16. C stored fp16; al dots fused in fp32-accumulator epilogue.
// BK=32: 16 HMMA per barrier round.
template <int H, typename AT>
__global__ __launch_bounds__(256, 2)
void gemm_mma_al(const AT* __restrict__ A, const float* __restrict__ B,
                 __half* __restrict__ C,
                 const float* __restrict__ asrc, const float* __restrict__ adst,
                 float* __restrict__ als, float* __restrict__ ald,
                 int M, int K, int N_) {
    __shared__ alignas(16) __half As[BM][APAD];   // [m][k], k contiguous
    __shared__ alignas(16) __half Bs[BN][BPAD];   // [n][k], k contiguous
    __shared__ float red_s[2][BM], red_d[2][BM];

    const int t    = threadIdx.x;
    const int lane = t & 31, wid = t >> 5;
    const int wm = wid & 3, wn = wid >> 2;      // 4x2 warp grid (32x32 warp tile)
    const int grp = lane >> 2, tig = lane & 3;
    const int head = blockIdx.x;
    const int row0 = blockIdx.y * BM;
    const int col0 = head * BN;

    float acc[2][4][4] = {};

    for (int k0 = 0; k0 < K; k0 += BK) {
        // ---- stage A: [BM][BK] fp16, thread owns 16 k-contiguous halves ----
        {
            int rl = t >> 1, c16 = (t & 1) * 16;
            int gr = row0 + rl;
            __half2 hv[8];
            if constexpr (sizeof(AT) == 4) {
                float4 v[4];
                #pragma unroll
                for (int j = 0; j < 4; j++) v[j] = make_float4(0.f, 0.f, 0.f, 0.f);
                if (gr < M) {
                    #pragma unroll
                    for (int j = 0; j < 4; j++)
                        v[j] = *(const float4*)&A[(size_t)gr * K + k0 + c16 + j * 4];
                }
                #pragma unroll
                for (int j = 0; j < 4; j++) {
                    hv[j * 2 + 0] = __floats2half2_rn(v[j].x, v[j].y);
                    hv[j * 2 + 1] = __floats2half2_rn(v[j].z, v[j].w);
                }
            } else {
                uint4 u0 = make_uint4(0u, 0u, 0u, 0u), u1 = u0;
                if (gr < M) {
                    u0 = *(const uint4*)&A[(size_t)gr * K + k0 + c16];
                    u1 = *(const uint4*)&A[(size_t)gr * K + k0 + c16 + 8];
                }
                *(uint4*)&hv[0] = u0;
                *(uint4*)&hv[4] = u1;
            }
            *(uint4*)&As[rl][c16]     = *(uint4*)&hv[0];
            *(uint4*)&As[rl][c16 + 8] = *(uint4*)&hv[4];
        }
        // ---- stage B: [BN][BK] fp16 (transpose of gmem [K][N_]) ----
        {
            int kk = t >> 3, n8 = (t & 7) * 8;
            float4 v1 = *(const float4*)&B[(size_t)(k0 + kk) * N_ + col0 + n8];
            float4 v2 = *(const float4*)&B[(size_t)(k0 + kk) * N_ + col0 + n8 + 4];
            Bs[n8 + 0][kk] = __float2half_rn(v1.x);
            Bs[n8 + 1][kk] = __float2half_rn(v1.y);
            Bs[n8 + 2][kk] = __float2half_rn(v1.z);
            Bs[n8 + 3][kk] = __float2half_rn(v1.w);
            Bs[n8 + 4][kk] = __float2half_rn(v2.x);
            Bs[n8 + 5][kk] = __float2half_rn(v2.y);
            Bs[n8 + 6][kk] = __float2half_rn(v2.z);
            Bs[n8 + 7][kk] = __float2half_rn(v2.w);
        }
        __syncthreads();

        // ---- 2 k-chunks of 16: fragments + 8 HMMA each ----
        #pragma unroll
        for (int kc = 0; kc < BK; kc += 16) {
            unsigned a[2][4], b[4][2];
            #pragma unroll
            for (int mt = 0; mt < 2; mt++) {
                int m0 = wm * 32 + mt * 16;
                a[mt][0] = *(const unsigned*)&As[m0 + grp][kc + tig * 2];
                a[mt][1] = *(const unsigned*)&As[m0 + grp + 8][kc + tig * 2];
                a[mt][2] = *(const unsigned*)&As[m0 + grp][kc + tig * 2 + 8];
                a[mt][3] = *(const unsigned*)&As[m0 + grp + 8][kc + tig * 2 + 8];
            }
            #pragma unroll
            for (int nt = 0; nt < 4; nt++) {
                int n0 = wn * 32 + nt * 8;
                b[nt][0] = *(const unsigned*)&Bs[n0 + grp][kc + tig * 2];
                b[nt][1] = *(const unsigned*)&Bs[n0 + grp][kc + tig * 2 + 8];
            }
            #pragma unroll
            for (int mt = 0; mt < 2; mt++)
                #pragma unroll
                for (int nt = 0; nt < 4; nt++)
                    mma_f16(acc[mt][nt], a[mt], b[nt]);
        }
        __syncthreads();
    }

    // ---- epilogue: fp16 store + fused al_src/al_dst dots (fp32) ----
    float ps[2][2] = {}, pd[2][2] = {};
    #pragma unroll
    for (int mt = 0; mt < 2; mt++) {
        int r0 = row0 + wm * 32 + mt * 16 + grp;
        #pragma unroll
        for (int nt = 0; nt < 4; nt++) {
            int cih = wn * 32 + nt * 8 + tig * 2;
            float c0 = acc[mt][nt][0], c1 = acc[mt][nt][1];
            float c2 = acc[mt][nt][2], c3 = acc[mt][nt][3];
            if (r0 < M)
                *(__half2*)&C[(size_t)r0 * N_ + col0 + cih] = __floats2half2_rn(c0, c1);
            if (r0 + 8 < M)
                *(__half2*)&C[(size_t)(r0 + 8) * N_ + col0 + cih] = __floats2half2_rn(c2, c3);
            float as0 = asrc[head * 64 + cih], as1 = asrc[head * 64 + cih + 1];
            float ad0 = adst[head * 64 + cih], ad1 = adst[head * 64 + cih + 1];
            ps[mt][0] += c0 * as0 + c1 * as1;  ps[mt][1] += c2 * as0 + c3 * as1;
            pd[mt][0] += c0 * ad0 + c1 * ad1;  pd[mt][1] += c2 * ad0 + c3 * ad1;
        }
    }
    #pragma unroll
    for (int mt = 0; mt < 2; mt++)
        #pragma unroll
        for (int rh = 0; rh < 2; rh++) {
            float s = ps[mt][rh], d = pd[mt][rh];
            s += __shfl_xor_sync(0xffffffffu, s, 1);
            s += __shfl_xor_sync(0xffffffffu, s, 2);
            d += __shfl_xor_sync(0xffffffffu, d, 1);
            d += __shfl_xor_sync(0xffffffffu, d, 2);
            if (tig == 0) {
                int rloc = wm * 32 + mt * 16 + rh * 8 + grp;
                red_s[wn][rloc] = s;
                red_d[wn][rloc] = d;
            }
        }
    __syncthreads();
    if (t < BM) {
        int row = row0 + t;
        if (row < M) {
            als[(size_t)row * H + head] = red_s[0][t] + red_s[1][t];
            ald[(size_t)row * H + head] = red_d[0][t] + red_d[1][t];
        }
    }
}

// ---------------- single-pass softmax aggregation (R7 scalar form) ----------
// softmax-weighted sum = (Σ e_i·v_i) / (Σ e_i). One edge loop, scalar fp32
// accumulators (32 regs, high occupancy). Edge list read as int4.
template <int H, int TC, bool DO_ELU, typename OutT>
__global__ __launch_bounds__(256)
void csr_aggregate(const __half* __restrict__ feat,
                   const float* __restrict__ als,
                   const float* __restrict__ ald,
                   const float* __restrict__ bias,
                   OutT* __restrict__ out) {
    int gw = (blockIdx.x * blockDim.x + threadIdx.x) >> 5;   // destination node
    if (gw >= NN) return;
    const int lane = threadIdx.x & 31;
    constexpr int FPL = TC / 32;                              // 8 / 2 halves per lane
    const int col = lane * FPL;
    const int myh = (H == 1) ? 0 : (col >> 6);

    const float aldh = ald[gw * H + myh];
    const int dg = min(g_cursor[gw], CAP);
    const int* lst = &g_csr[(size_t)gw * CAP];
    const int4* lst4 = (const int4*)lst;      // 512B-aligned (CAP ints)

    float den = 0.f;
    float acc[FPL] = {};

    auto edge = [&](int s) {
        float l = als[s * H + myh] + aldh;
        l = fmaxf(l, 0.f) + 0.2f * fminf(l, 0.f);
        float e = __expf(l);
        den += e;
        const __half* row = &feat[(size_t)s * TC + col];
        if constexpr (FPL == 8) {
            uint4 u = *(const uint4*)row;
            const __half2* hp = (const __half2*)&u;
            #pragma unroll
            for (int j = 0; j < 4; j++) {
                float2 f = __half22float2(hp[j]);
                acc[j * 2 + 0] += e * f.x;
                acc[j * 2 + 1] += e * f.y;
            }
        } else {
            float2 f = __half22float2(*(const __half2*)row);
            acc[0] += e * f.x;
            acc[1] += e * f.y;
        }
    };

    const int nv = dg >> 2;
    for (int iv = 0; iv < nv; iv++) {
        int4 q = lst4[iv];
        edge(q.x); edge(q.y); edge(q.z); edge(q.w);
    }
    for (int i = nv * 4; i < dg; i++) edge(lst[i]);

    // epilogue: normalize, bias (+ elu), store
    const float rden = 1.f / fmaxf(den, 1e-16f);
    #pragma unroll
    for (int j = 0; j < FPL; j++) {
        float v = acc[j] * rden + bias[col + j];
        if constexpr (DO_ELU) v = v > 0.f ? v : expm1f(v);
        acc[j] = v;
    }
    if constexpr (sizeof(OutT) == 2) {
        __half2 hv[FPL / 2];
        #pragma unroll
        for (int j = 0; j < FPL / 2; j++)
            hv[j] = __floats2half2_rn(acc[j * 2], acc[j * 2 + 1]);
        if constexpr (FPL == 8)
            *(uint4*)&out[(size_t)gw * TC + col] = *(uint4*)hv;
        else
            *(__half2*)&out[(size_t)gw * TC + col] = hv[0];
    } else {
        if constexpr (FPL == 8) {
            *(float4*)&out[(size_t)gw * TC + col]     = make_float4(acc[0], acc[1], acc[2], acc[3]);
            *(float4*)&out[(size_t)gw * TC + col + 4] = make_float4(acc[4], acc[5], acc[6], acc[7]);
        } else {
            *(float2*)&out[(size_t)gw * TC + col] = make_float2(acc[0], acc[1]);
        }
    }
}

// ---------------- launch -----------------------------------------------------
extern "C" void kernel_launch(void* const* d_in, const int* in_sizes, int n_in,
                              void* d_out, int out_size) {
    (void)n_in; (void)in_sizes; (void)out_size;
    const float* x      = (const float*)d_in[0];
    const int*   ei     = (const int*)d_in[1];
    const float* W1     = (const float*)d_in[2];
    const float* a_src1 = (const float*)d_in[3];
    const float* a_dst1 = (const float*)d_in[4];
    const float* b1     = (const float*)d_in[5];
    const float* W2     = (const float*)d_in[6];
    const float* a_src2 = (const float*)d_in[7];
    const float* a_dst2 = (const float*)d_in[8];
    const float* b2     = (const float*)d_in[9];
    float* dout = (float*)d_out;

    __half *h1, *out1, *h2;
    float *alsrc1, *aldst1, *alsrc2, *aldst2;
    cudaGetSymbolAddress((void**)&h1,     g_h1);
    cudaGetSymbolAddress((void**)&out1,   g_out1);
    cudaGetSymbolAddress((void**)&h2,     g_h2);
    cudaGetSymbolAddress((void**)&alsrc1, g_alsrc1);
    cudaGetSymbolAddress((void**)&aldst1, g_aldst1);
    cudaGetSymbolAddress((void**)&alsrc2, g_alsrc2);
    cudaGetSymbolAddress((void**)&aldst2, g_aldst2);

    const int T = 256;
    // 0) adjacency build (shared by both layers)
    init_kernel<<<(NN + T - 1) / T, T>>>();
    fill_adj<<<(ETOT + T - 1) / T, T>>>(ei);
    // 1) h1 = x @ W1 (+ als1/ald1 fused), fp16 HMMA, h1 stored fp16
    {
        dim3 g(C1 / BN, (NN + BM - 1) / BM);
        gemm_mma_al<H1N, float><<<g, 256>>>(x, W1, h1, a_src1, a_dst1,
                                            alsrc1, aldst1, NN, 128, C1);
    }
    // 2) single-pass softmax + aggregate + bias + elu  (layer 1), out1 fp16
    csr_aggregate<H1N, C1, true, __half><<<(NN * 32 + T - 1) / T, T>>>(
        h1, alsrc1, aldst1, b1, out1);
    // 3) h2 = out1 @ W2 (+ als2/ald2 fused), fp16 A direct, fp16 HMMA
    {
        dim3 g(C2 / BN, (NN + BM - 1) / BM);
        gemm_mma_al<1, __half><<<g, 256>>>(out1, W2, h2, a_src2, a_dst2,
                                           alsrc2, aldst2, NN, C1, C2);
    }
    // 4) single-pass softmax + aggregate + bias  (layer 2, fp32 to d_out)
    csr_aggregate<1, C2, false, float><<<(NN * 32 + T - 1) / T, T>>>(
        h2, alsrc2, aldst2, b2, dout);
}